// round 10
// baseline (speedup 1.0000x reference)
#include <cuda_runtime.h>
#include <cstdint>

// CrossAttention collapses: K/V are one visual_features vector broadcast over
// all T keys; softmax over identical logits is uniform, so y == v everywhere:
//   out[b,t,:] = ((vf[b] @ Wv + bv) @ Wp + bp)   broadcast over t.
// x / Wq / bq / Wk / bk are mathematically dead.
//
// R8/R9: (a) projections process all 4 batches per block -> weights read once
// (4MB not 16MB per GEMM); (b) broadcast via cp.async.bulk (TMA) stores from
// a single staged SMEM row -> bypasses the STG.128 per-instruction issue
// floor (~6.7us) of the per-thread store broadcast. R9: bulk-copy size in a
// register (immediate operand was the only nonstandard construct in R8's
// failed run).

#define CDIM  1024
#define BDIM  4
#define TDIM  1024
#define KS    32              // split-K chunks for both projections
#define ROWS  (CDIM / KS)     // 32 reduction rows per chunk
#define JT    128             // threads per proj block
#define JSPAN (JT * 4)        // 512 columns per block
#define JBLK  (CDIM / JSPAN)  // 2
#define TROWS 64              // t-rows per bcast block (grid 16 x 4)

__device__ float g_pvv[KS][BDIM][CDIM];  // partials of vf @ Wv
__device__ float g_pr [KS][BDIM][CDIM];  // partials of vv @ Wp

__device__ __forceinline__ uint32_t smem_u32(const void* p)
{
    uint32_t a;
    asm("{ .reg .u64 t; cvta.to.shared.u64 t, %1; cvt.u32.u64 %0, t; }"
        : "=r"(a) : "l"(p));
    return a;
}

// ---------------------------------------------------------------------------
// K1: g_pvv[k][b][j] = sum_{i in chunk k} vf[b,i] * Wv[i,j], all 4 b per block.
// grid (JBLK, KS) = (2, 32), 128 threads.
__global__ __launch_bounds__(JT) void vv_partial_kernel(
    const float* __restrict__ vf, const float* __restrict__ Wv)
{
    const int jx = blockIdx.x, k = blockIdx.y;
    const int j0 = jx * JSPAN + threadIdx.x * 4;

    __shared__ float s_in[BDIM][ROWS];
    {
        const int bb = threadIdx.x >> 5;        // 0..3
        const int i  = threadIdx.x & 31;        // 0..31
        s_in[bb][i] = vf[bb * CDIM + k * ROWS + i];
    }
    __syncthreads();

    float4 acc[BDIM];
    #pragma unroll
    for (int bb = 0; bb < BDIM; ++bb) acc[bb] = make_float4(0.f, 0.f, 0.f, 0.f);

    #pragma unroll
    for (int i = 0; i < ROWS; ++i) {
        const float4 w = __ldg((const float4*)&Wv[(k * ROWS + i) * CDIM + j0]);
        #pragma unroll
        for (int bb = 0; bb < BDIM; ++bb) {
            const float s = s_in[bb][i];
            acc[bb].x += s * w.x; acc[bb].y += s * w.y;
            acc[bb].z += s * w.z; acc[bb].w += s * w.w;
        }
    }
    #pragma unroll
    for (int bb = 0; bb < BDIM; ++bb)
        *(float4*)&g_pvv[k][bb][j0] = acc[bb];
}

// ---------------------------------------------------------------------------
// K2: reduce the needed vv slice for all 4 b (32 vals x 32 partials + bv),
// then g_pr[k][b][j] = sum_{i in chunk k} vv[b,i] * Wp[i,j].
// grid (JBLK, KS) = (2, 32), 128 threads.
__global__ __launch_bounds__(JT) void r_partial_kernel(
    const float* __restrict__ bv, const float* __restrict__ Wp)
{
    const int jx = blockIdx.x, k = blockIdx.y;
    const int j0 = jx * JSPAN + threadIdx.x * 4;

    __shared__ float s_in[BDIM][ROWS];
    {
        const int bb = threadIdx.x >> 5;
        const int i  = threadIdx.x & 31;
        float s = bv[k * ROWS + i];
        #pragma unroll
        for (int kk = 0; kk < KS; ++kk)
            s += g_pvv[kk][bb][k * ROWS + i];
        s_in[bb][i] = s;
    }
    __syncthreads();

    float4 acc[BDIM];
    #pragma unroll
    for (int bb = 0; bb < BDIM; ++bb) acc[bb] = make_float4(0.f, 0.f, 0.f, 0.f);

    #pragma unroll
    for (int i = 0; i < ROWS; ++i) {
        const float4 w = __ldg((const float4*)&Wp[(k * ROWS + i) * CDIM + j0]);
        #pragma unroll
        for (int bb = 0; bb < BDIM; ++bb) {
            const float s = s_in[bb][i];
            acc[bb].x += s * w.x; acc[bb].y += s * w.y;
            acc[bb].z += s * w.z; acc[bb].w += s * w.w;
        }
    }
    #pragma unroll
    for (int bb = 0; bb < BDIM; ++bb)
        *(float4*)&g_pr[k][bb][j0] = acc[bb];
}

// ---------------------------------------------------------------------------
// K3: final reduce + TMA-bulk broadcast.
// Each thread: r4 = bp[j0..3] + sum_{kk<32} g_pr[kk][b][j0..3]  -> SMEM row.
// Then thread 0 issues TROWS cp.async.bulk 4KB copies (same SMEM source) to
// consecutive t rows. grid (TDIM/TROWS, BDIM) = (16, 4), 256 threads.
__global__ __launch_bounds__(256) void rb_kernel(
    const float* __restrict__ bp, float* __restrict__ out)
{
    __shared__ __align__(128) float s_row[CDIM];

    const int tid = threadIdx.x;           // 0..255
    const int b   = blockIdx.y;
    const int t0  = blockIdx.x * TROWS;
    const int j0  = tid * 4;

    float4 acc = __ldg((const float4*)&bp[j0]);
    #pragma unroll
    for (int kk = 0; kk < KS; ++kk) {
        const float4 p = __ldg((const float4*)&g_pr[kk][b][j0]);
        acc.x += p.x; acc.y += p.y; acc.z += p.z; acc.w += p.w;
    }
    *(float4*)&s_row[j0] = acc;
    __syncthreads();

    // Make generic-proxy SMEM writes visible to the async (TMA) proxy.
    asm volatile("fence.proxy.async.shared::cta;" ::: "memory");

    if (tid == 0) {
        const uint32_t src = smem_u32(s_row);
        const uint32_t nbytes = CDIM * 4;       // 4096, register operand
        float* dst = out + (size_t)(b * TDIM + t0) * CDIM;
        #pragma unroll 4
        for (int t = 0; t < TROWS; ++t) {
            asm volatile(
                "cp.async.bulk.global.shared::cta.bulk_group [%0], [%1], %2;"
                :: "l"(dst + (size_t)t * CDIM), "r"(src), "r"(nbytes)
                : "memory");
        }
        asm volatile("cp.async.bulk.commit_group;" ::: "memory");
        asm volatile("cp.async.bulk.wait_group 0;" ::: "memory");
    }
    __syncthreads();   // keep SMEM alive until copies complete
}

extern "C" void kernel_launch(void* const* d_in, const int* in_sizes, int n_in,
                              void* d_out, int out_size)
{
    (void)in_sizes; (void)n_in; (void)out_size;
    const float* vf = (const float*)d_in[1];
    const float* Wv = (const float*)d_in[6];
    const float* bv = (const float*)d_in[7];
    const float* Wp = (const float*)d_in[8];
    const float* bp = (const float*)d_in[9];

    dim3 g1(JBLK, KS);                        // 64 blocks
    vv_partial_kernel<<<g1, JT>>>(vf, Wv);

    dim3 g2(JBLK, KS);                        // 64 blocks
    r_partial_kernel<<<g2, JT>>>(bv, Wp);

    dim3 g3(TDIM / TROWS, BDIM);              // 16 x 4 = 64 blocks
    rb_kernel<<<g3, 256>>>(bp, (float*)d_out);
}

// round 14
// speedup vs baseline: 1.2261x; 1.2261x over previous
#include <cuda_runtime.h>
#include <cstdint>

// CrossAttention collapses: K/V are one visual_features vector broadcast over
// all T keys; softmax over identical logits is uniform, so y == v everywhere:
//   out[b,t,:] = ((vf[b] @ Wv + bv) @ Wp + bp)   broadcast over t.
// x / Wq / bq / Wk / bk are mathematically dead.
//
// R10: exact R4 structure (best measured, 15.4us) with ONE change: the
// broadcast kernel uses cp.async.bulk (TMA) 32KB copies from an 8-row SMEM
// image instead of ~1M STG.128 (whose per-instruction issue cost is the
// 6.7us floor). R9's regression is attributed to the batched projections
// (64-block grids, latency-bound warm) — reverted here.

#define CDIM  1024
#define BDIM  4
#define TDIM  1024
#define KS    32              // split-K chunk count
#define ROWS  (CDIM / KS)     // 32 reduction rows per chunk
#define JT    128             // threads per proj block
#define JSPAN (JT * 4)        // 512 output columns per block
#define JBLK  (CDIM / JSPAN)  // 2
#define BROWS 8               // rows replicated in the SMEM image (32KB)
#define RPB   16              // t-rows written per bcast block

__device__ float g_pvv[KS][BDIM][CDIM];  // partials of vf @ Wv
__device__ float g_pr [KS][BDIM][CDIM];  // partials of vv @ Wp
__device__ float g_r  [BDIM][CDIM];      // final row to broadcast

__device__ __forceinline__ uint32_t smem_u32(const void* p)
{
    uint32_t a;
    asm("{ .reg .u64 t; cvta.to.shared.u64 t, %1; cvt.u32.u64 %0, t; }"
        : "=r"(a) : "l"(p));
    return a;
}

// ---------------------------------------------------------------------------
// K1: g_pvv[k][b][j] = sum_{i in chunk k} vf[b,i] * Wv[i,j]
// grid (JBLK, BDIM, KS) = (2,4,32), 128 threads.  (proven R3/R4 kernel)
__global__ __launch_bounds__(JT) void vv_partial_kernel(
    const float* __restrict__ vf, const float* __restrict__ Wv)
{
    const int jx = blockIdx.x, b = blockIdx.y, k = blockIdx.z;
    const int j0 = jx * JSPAN + threadIdx.x * 4;

    __shared__ float s_in[ROWS];
    if (threadIdx.x < ROWS)
        s_in[threadIdx.x] = vf[b * CDIM + k * ROWS + threadIdx.x];
    __syncthreads();

    float4 acc = make_float4(0.f, 0.f, 0.f, 0.f);
    #pragma unroll
    for (int i = 0; i < ROWS; ++i) {
        const float4 w = __ldg((const float4*)&Wv[(k * ROWS + i) * CDIM + j0]);
        const float s = s_in[i];
        acc.x += s * w.x; acc.y += s * w.y; acc.z += s * w.z; acc.w += s * w.w;
    }
    *(float4*)&g_pvv[k][b][j0] = acc;
}

// ---------------------------------------------------------------------------
// K2: reduce the needed vv slice (32 values x 32 partials + bv) in shared,
// then partials of vv @ Wp. grid (JBLK, BDIM, KS), 128 threads. (proven)
__global__ __launch_bounds__(JT) void r_partial_kernel(
    const float* __restrict__ bv, const float* __restrict__ Wp)
{
    const int jx = blockIdx.x, b = blockIdx.y, k = blockIdx.z;
    const int j0 = jx * JSPAN + threadIdx.x * 4;

    __shared__ float s_red[4][ROWS];
    __shared__ float s_in[ROWS];

    {
        const int i  = threadIdx.x & 31;
        const int kg = threadIdx.x >> 5;
        float s = 0.f;
        #pragma unroll
        for (int kk = kg * 8; kk < kg * 8 + 8; ++kk)
            s += g_pvv[kk][b][k * ROWS + i];
        s_red[kg][i] = s;
    }
    __syncthreads();
    if (threadIdx.x < ROWS)
        s_in[threadIdx.x] = s_red[0][threadIdx.x] + s_red[1][threadIdx.x]
                          + s_red[2][threadIdx.x] + s_red[3][threadIdx.x]
                          + bv[k * ROWS + threadIdx.x];
    __syncthreads();

    float4 acc = make_float4(0.f, 0.f, 0.f, 0.f);
    #pragma unroll
    for (int i = 0; i < ROWS; ++i) {
        const float4 w = __ldg((const float4*)&Wp[(k * ROWS + i) * CDIM + j0]);
        const float s = s_in[i];
        acc.x += s * w.x; acc.y += s * w.y; acc.z += s * w.z; acc.w += s * w.w;
    }
    *(float4*)&g_pr[k][b][j0] = acc;
}

// ---------------------------------------------------------------------------
// K3: g_r[b][j] = bp[j] + sum_k g_pr[k][b][j]. 4096 outputs. (proven)
__global__ __launch_bounds__(512) void r_reduce_kernel(const float* __restrict__ bp)
{
    const int idx = blockIdx.x * 512 + threadIdx.x;   // 0..4095
    const int b = idx >> 10;
    const int j = idx & (CDIM - 1);
    float s = bp[j];
    #pragma unroll
    for (int k = 0; k < KS; ++k)
        s += g_pr[k][b][j];
    g_r[b][j] = s;
}

// ---------------------------------------------------------------------------
// K4 (new): TMA-bulk broadcast. Each thread loads its g_r float4 once and
// replicates it into an 8-row SMEM image (32KB); thread 0 then issues two
// 32KB cp.async.bulk copies covering 16 contiguous t-rows.
// grid (TDIM/RPB, BDIM) = (64, 4) = 256 blocks, 256 threads.
__global__ __launch_bounds__(256) void tma_bcast_kernel(float* __restrict__ out)
{
    __shared__ __align__(128) float s_img[BROWS * CDIM];   // 32 KB

    const int tid = threadIdx.x;           // 0..255 == column/4
    const int b   = blockIdx.y;
    const int t0  = blockIdx.x * RPB;

    const float4 v = *(const float4*)&g_r[b][tid * 4];
    #pragma unroll
    for (int rr = 0; rr < BROWS; ++rr)
        *(float4*)&s_img[rr * CDIM + tid * 4] = v;
    __syncthreads();
    asm volatile("fence.proxy.async.shared::cta;" ::: "memory");

    if (tid == 0) {
        const uint32_t src    = smem_u32(s_img);
        const uint32_t nbytes = BROWS * CDIM * 4;          // 32768
        float* dst = out + (size_t)(b * TDIM + t0) * CDIM;
        asm volatile("cp.async.bulk.global.shared::cta.bulk_group [%0], [%1], %2;"
                     :: "l"(dst), "r"(src), "r"(nbytes) : "memory");
        asm volatile("cp.async.bulk.global.shared::cta.bulk_group [%0], [%1], %2;"
                     :: "l"(dst + BROWS * CDIM), "r"(src), "r"(nbytes) : "memory");
        asm volatile("cp.async.bulk.commit_group;" ::: "memory");
        asm volatile("cp.async.bulk.wait_group 0;" ::: "memory");
    }
    __syncthreads();   // keep SMEM alive until the copies complete
}

extern "C" void kernel_launch(void* const* d_in, const int* in_sizes, int n_in,
                              void* d_out, int out_size)
{
    (void)in_sizes; (void)n_in; (void)out_size;
    const float* vf = (const float*)d_in[1];
    const float* Wv = (const float*)d_in[6];
    const float* bv = (const float*)d_in[7];
    const float* Wp = (const float*)d_in[8];
    const float* bp = (const float*)d_in[9];

    dim3 pgrid(JBLK, BDIM, KS);                       // 256 blocks
    vv_partial_kernel<<<pgrid, JT>>>(vf, Wv);
    r_partial_kernel <<<pgrid, JT>>>(bv, Wp);
    r_reduce_kernel  <<<BDIM * CDIM / 512, 512>>>(bp);

    dim3 bgrid(TDIM / RPB, BDIM);                     // 64 x 4 = 256 blocks
    tma_bcast_kernel<<<bgrid, 256>>>((float*)d_out);
}